// round 5
// baseline (speedup 1.0000x reference)
#include <cuda_runtime.h>
#include <cuda_bf16.h>
#include <cstdint>

#define Dv 512
#define Rv 64
#define TM 128
#define NTHREADS 256

// ---------------------------------------------------------------------------
// Device scratch
// ---------------------------------------------------------------------------
__device__ float g_Vt[Rv * Dv];   // normalized reflections, [r][d]
__device__ float g_G [Rv * Rv];   // Gram matrix
__device__ float g_W [Rv * Rv];   // W = M^-1 (upper tri), A = 2 V W
// Pre-packed bf16 hi/lo operand tiles, 128B rows, SW128-swizzled
__device__ __align__(16) __nv_bfloat16 g_Abh[8 * 64 * 64];   // chunk c: [r][kk]
__device__ __align__(16) __nv_bfloat16 g_Abl[8 * 64 * 64];
__device__ __align__(16) __nv_bfloat16 g_Vbh[4 * 128 * 64];  // n-chunk j: [n][r]
__device__ __align__(16) __nv_bfloat16 g_Vbl[4 * 128 * 64];

// ---------------------------------------------------------------------------
// Helpers
// ---------------------------------------------------------------------------
#define SWZ(o) ((o) ^ (((o) >> 3) & 0x70))

__device__ __forceinline__ uint32_t smem_to_u32(const void* p) {
    uint32_t a;
    asm("{ .reg .u64 t; cvta.to.shared.u64 t, %1; cvt.u32.u64 %0, t; }" : "=r"(a) : "l"(p));
    return a;
}
__device__ __forceinline__ void ldsm4(uint32_t* r, uint32_t addr) {
    asm volatile("ldmatrix.sync.aligned.m8n8.x4.shared.b16 {%0,%1,%2,%3}, [%4];"
                 : "=r"(r[0]), "=r"(r[1]), "=r"(r[2]), "=r"(r[3]) : "r"(addr));
}
__device__ __forceinline__ void mma16816(float* c, const uint32_t* a,
                                         uint32_t b0, uint32_t b1) {
    asm volatile("mma.sync.aligned.m16n8k16.row.col.f32.bf16.bf16.f32 "
                 "{%0,%1,%2,%3}, {%4,%5,%6,%7}, {%8,%9}, {%0,%1,%2,%3};"
                 : "+f"(c[0]), "+f"(c[1]), "+f"(c[2]), "+f"(c[3])
                 : "r"(a[0]), "r"(a[1]), "r"(a[2]), "r"(a[3]), "r"(b0), "r"(b1));
}
__device__ __forceinline__ void sts128(uint32_t a, uint32_t x, uint32_t y,
                                       uint32_t z, uint32_t w) {
    asm volatile("st.shared.v4.b32 [%0], {%1,%2,%3,%4};"
                 :: "r"(a), "r"(x), "r"(y), "r"(z), "r"(w) : "memory");
}
__device__ __forceinline__ float4 lds128(uint32_t a) {
    float4 v;
    asm volatile("ld.shared.v4.f32 {%0,%1,%2,%3}, [%4];"
                 : "=f"(v.x), "=f"(v.y), "=f"(v.z), "=f"(v.w) : "r"(a));
    return v;
}
__device__ __forceinline__ void cpasync16(uint32_t dst, const void* src) {
    asm volatile("cp.async.cg.shared.global [%0], [%1], 16;"
                 :: "r"(dst), "l"(src) : "memory");
}
#define CP_COMMIT() asm volatile("cp.async.commit_group;" ::: "memory")
#define CP_WAIT(N)  asm volatile("cp.async.wait_group %0;" :: "n"(N) : "memory")

__device__ __forceinline__ uint32_t cvt2(float f0, float f1) {
    uint32_t r;
    asm("cvt.rn.bf16x2.f32 %0, %1, %2;" : "=r"(r) : "f"(f1), "f"(f0));
    return r;
}
__device__ __forceinline__ float bl(uint32_t h) { return __uint_as_float(h << 16); }
__device__ __forceinline__ float bh(uint32_t h) { return __uint_as_float(h & 0xFFFF0000u); }

// ---------------------------------------------------------------------------
// Precompute 1: normalize columns -> g_Vt
// ---------------------------------------------------------------------------
__global__ void k_norm(const float* __restrict__ P) {
    int r = blockIdx.x, t = threadIdx.x;
    __shared__ float red[256];
    float s = 0.f;
    for (int d = t; d < Dv; d += 256) { float v = P[d * Rv + r]; s += v * v; }
    red[t] = s; __syncthreads();
    for (int o = 128; o > 0; o >>= 1) { if (t < o) red[t] += red[t + o]; __syncthreads(); }
    float rin = rsqrtf(red[0]);
    for (int d = t; d < Dv; d += 256) g_Vt[r * Dv + d] = P[d * Rv + r] * rin;
}

// ---------------------------------------------------------------------------
// Precompute 2: Gram matrix; blocks 0..3 additionally pack V n-chunk j=blockIdx
// ---------------------------------------------------------------------------
__global__ void k_gram_packV() {
    __shared__ float sV[64][129];
    int k = blockIdx.x, tid = threadIdx.x, w = tid >> 5, lane = tid & 31;
    for (int j = w; j < Rv; j += 8) {
        float s = 0.f;
        for (int d = lane; d < Dv; d += 32) s += g_Vt[j * Dv + d] * g_Vt[k * Dv + d];
        #pragma unroll
        for (int o = 16; o; o >>= 1) s += __shfl_down_sync(0xFFFFFFFFu, s, o);
        if (lane == 0) g_G[k * Rv + j] = s;
    }
    if (k < 4) {
        int j = k;
        for (int idx = tid; idx < 8192; idx += 256) {
            int r = idx >> 7, n = idx & 127;
            sV[r][n] = g_Vt[r * Dv + j * 128 + n];
        }
        __syncthreads();
        for (int idx = tid; idx < 8192; idx += 256) {
            int n = idx >> 6, r = idx & 63;
            float v = sV[r][n];
            __nv_bfloat16 h = __float2bfloat16_rn(v);
            float lo = v - __bfloat162float(h);
            uint32_t off = j * 16384 + SWZ((uint32_t)(n * 128 + r * 2));
            *(__nv_bfloat16*)((char*)g_Vbh + off) = h;
            *(__nv_bfloat16*)((char*)g_Vbl + off) = __float2bfloat16_rn(lo);
        }
    }
}

// ---------------------------------------------------------------------------
// Precompute 3: W = M^-1 via 64 parallel back-substitutions (warp per column)
// M upper-tri: M[i][k] = 2*G[k][i] (i<k), diag 1.  a_k = 2 (V W)_k.
// ---------------------------------------------------------------------------
__global__ __launch_bounds__(1024) void k_winv() {
    __shared__ float sGT[64][65];   // sGT[i][j] = 2*G[j][i]
    __shared__ float sw[64][64];    // per-column solution buffers [k][i]
    int tid = threadIdx.x, w = tid >> 5, lane = tid & 31;
    for (int idx = tid; idx < 4096; idx += 1024) {
        int a = idx >> 6, b = idx & 63;          // g_G[a*64+b] = G[a][b]
        sGT[b][a] = 2.f * g_G[idx];
    }
    __syncthreads();
    for (int k = w; k < 64; k += 32) {
        for (int i = lane; i < 64; i += 32) sw[k][i] = (i == k) ? 1.f : 0.f;
        __syncwarp();
        for (int i = k - 1; i >= 0; i--) {
            float s = 0.f;
            for (int j = i + 1 + lane; j <= k; j += 32)
                s += sGT[i][j] * sw[k][j];
            #pragma unroll
            for (int o = 16; o; o >>= 1) s += __shfl_xor_sync(0xFFFFFFFFu, s, o);
            if (lane == 0) sw[k][i] = -s;
            __syncwarp();
        }
    }
    __syncthreads();
    for (int idx = tid; idx < 4096; idx += 1024) {
        int j = idx >> 6, k = idx & 63;
        g_W[idx] = (j < k) ? sw[k][j] : (j == k ? 1.f : 0.f);
    }
}

// ---------------------------------------------------------------------------
// Precompute 4: A' chunk c = 2 * (V W) slice, bf16 hi/lo packed + swizzled
// ---------------------------------------------------------------------------
__global__ __launch_bounds__(256) void k_packA2() {
    __shared__ float sV[64][68];    // [j][kk]  (68 floats -> 16B-aligned rows)
    __shared__ float sW2[64][68];   // [j][r]
    int c = blockIdx.x, tid = threadIdx.x;
    for (int idx = tid; idx < 4096; idx += 256) {
        int j = idx >> 6, q = idx & 63;
        sV[j][q]  = g_Vt[j * Dv + c * 64 + q];
        sW2[j][q] = g_W[idx];
    }
    __syncthreads();
    int r0 = (tid >> 4) << 2, kk0 = (tid & 15) << 2;
    float o[4][4] = {};
    for (int j = 0; j < 64; j++) {
        float4 vv = *(const float4*)&sV[j][kk0];
        float4 ww = *(const float4*)&sW2[j][r0];
        float va[4] = {vv.x, vv.y, vv.z, vv.w};
        float wa[4] = {ww.x, ww.y, ww.z, ww.w};
        #pragma unroll
        for (int a = 0; a < 4; a++)
            #pragma unroll
            for (int b = 0; b < 4; b++)
                o[a][b] += wa[a] * va[b];
    }
    #pragma unroll
    for (int a = 0; a < 4; a++)
        #pragma unroll
        for (int b = 0; b < 4; b++) {
            float v = 2.f * o[a][b];
            __nv_bfloat16 h = __float2bfloat16_rn(v);
            float lo = v - __bfloat162float(h);
            uint32_t off = c * 8192 + SWZ((uint32_t)((r0 + a) * 128 + (kk0 + b) * 2));
            *(__nv_bfloat16*)((char*)g_Abh + off) = h;
            *(__nv_bfloat16*)((char*)g_Abl + off) = __float2bfloat16_rn(lo);
        }
}

// ---------------------------------------------------------------------------
// Main kernel. smem (96KB, 2 CTA/SM):
//   [0,     32768)  stage: raw fp32 X chunk / V buffers 0,2 (hi+lo)
//   [32768, 49152)  Xh
//   [49152, 65536)  Xl
//   [65536, 98304)  A ping/pong (16K each) / V buffers 1,3 (hi+lo)
// ---------------------------------------------------------------------------
#define OFF_STAGE 0
#define OFF_XH    32768
#define OFF_XL    49152
#define OFF_A0    65536
#define OFF_A1    81920
#define SMEM_BYTES 98304

__global__ __launch_bounds__(NTHREADS, 2) void k_gemm(const float* __restrict__ x,
                                                      float* __restrict__ out,
                                                      const float* __restrict__ sldj,
                                                      float* __restrict__ outSldj) {
    extern __shared__ char smem[];
    uint32_t sb = smem_to_u32(smem);
    const uint32_t sStage = sb + OFF_STAGE;
    const uint32_t sXh = sb + OFF_XH;
    const uint32_t sXl = sb + OFF_XL;

    int tid = threadIdx.x, wid = tid >> 5, lane = tid & 31;
    int m0 = blockIdx.x * TM;
    int mw = wid << 4;

    uint32_t lrow = lane & 15;
    uint32_t lcolb = (lane >> 4) << 4;
    uint32_t xr = (lrow & 7) << 4;
    uint32_t arowb = (mw + lrow) * 128;

    auto issueX = [&](int c) {
        for (int idx = tid; idx < 2048; idx += NTHREADS) {
            int r = idx >> 4, i = idx & 15;
            uint32_t dst = sStage + r * 256 + (((uint32_t)(i * 16)) ^ ((r & 7) << 5));
            const char* src = (const char*)(x + (size_t)(m0 + r) * Dv + c * 64 + i * 4);
            cpasync16(dst, src);
        }
    };
    auto issueA = [&](int c, uint32_t buf) {
        const char* srch = (const char*)g_Abh + c * 8192;
        const char* srcl = (const char*)g_Abl + c * 8192;
        for (int idx = tid; idx < 512; idx += NTHREADS) {
            cpasync16(buf + idx * 16, srch + idx * 16);
            cpasync16(buf + 8192 + idx * 16, srcl + idx * 16);
        }
    };
    auto issueV = [&](int j, uint32_t bufh, uint32_t bufl) {
        const char* srch = (const char*)g_Vbh + j * 16384;
        const char* srcl = (const char*)g_Vbl + j * 16384;
        for (int idx = tid; idx < 1024; idx += NTHREADS) {
            cpasync16(bufh + idx * 16, srch + idx * 16);
            cpasync16(bufl + idx * 16, srcl + idx * 16);
        }
    };

    float acc[8][4];
    #pragma unroll
    for (int i = 0; i < 8; i++)
        acc[i][0] = acc[i][1] = acc[i][2] = acc[i][3] = 0.f;

    issueX(0); issueA(0, sb + OFF_A0); CP_COMMIT();

    // ================= Phase 1: Y = X A  (8 k-chunks of 64) =================
    for (int c = 0; c < 8; c++) {
        CP_WAIT(0);
        __syncthreads();
        #pragma unroll
        for (int p = 0; p < 4; p++) {
            int it = tid + p * NTHREADS;
            int row = it >> 3, g = it & 7;
            uint32_t sa = sStage + row * 256 + (((uint32_t)(g * 32)) ^ ((row & 7) << 5));
            float4 v0 = lds128(sa);
            float4 v1 = lds128(sa + 16);
            float f[8] = {v0.x, v0.y, v0.z, v0.w, v1.x, v1.y, v1.z, v1.w};
            uint32_t H[4], L[4];
            #pragma unroll
            for (int q = 0; q < 4; q++) {
                uint32_t h = cvt2(f[2 * q], f[2 * q + 1]);
                H[q] = h;
                L[q] = cvt2(f[2 * q] - bl(h), f[2 * q + 1] - bh(h));
            }
            uint32_t ad = row * 128 + (((uint32_t)(g * 16)) ^ ((row & 7) << 4));
            sts128(sXh + ad, H[0], H[1], H[2], H[3]);
            sts128(sXl + ad, L[0], L[1], L[2], L[3]);
        }
        __syncthreads();
        if (c < 7) {
            issueX(c + 1);
            issueA(c + 1, sb + ((c + 1) & 1 ? OFF_A1 : OFF_A0));
            CP_COMMIT();
        } else {
            issueV(0, sStage, sStage + 16384);   // stage free after conversion
            CP_COMMIT();
        }
        uint32_t bufAh = sb + ((c & 1) ? OFF_A1 : OFF_A0);
        uint32_t bufAl = bufAh + 8192;
        #pragma unroll
        for (int ks = 0; ks < 4; ks++) {
            uint32_t ic = (lcolb + ks * 32) ^ xr;
            uint32_t ah[4], al[4];
            ldsm4(ah, sXh + arowb + ic);
            ldsm4(al, sXl + arowb + ic);
            #pragma unroll
            for (int p = 0; p < 4; p++) {
                uint32_t ro = (lrow + p * 16) * 128;
                uint32_t bhr[4], blr[4];
                ldsm4(bhr, bufAh + ro + ic);
                ldsm4(blr, bufAl + ro + ic);
                mma16816(acc[2 * p],     ah, bhr[0], bhr[2]);
                mma16816(acc[2 * p],     ah, blr[0], blr[2]);
                mma16816(acc[2 * p],     al, bhr[0], bhr[2]);
                mma16816(acc[2 * p + 1], ah, bhr[1], bhr[3]);
                mma16816(acc[2 * p + 1], ah, blr[1], blr[3]);
                mma16816(acc[2 * p + 1], al, bhr[1], bhr[3]);
            }
        }
    }
    __syncthreads();                       // MMA(7) done reading A1
    issueV(1, sb + OFF_A0, sb + OFF_A1);   // V1 -> A region
    CP_COMMIT();

    // ======= Y: register repack acc (C-frag) -> phase-2 A-frags (hi/lo) =====
    // C frag of acc[2kb]/acc[2kb+1] maps exactly to A frag {a0,a1,a2,a3}.
    uint32_t yh[4][4], yl[4][4];
    #pragma unroll
    for (int kb = 0; kb < 4; kb++) {
        uint32_t h;
        h = cvt2(acc[2*kb][0],   acc[2*kb][1]);   yh[kb][0] = h;
        yl[kb][0] = cvt2(acc[2*kb][0] - bl(h),    acc[2*kb][1] - bh(h));
        h = cvt2(acc[2*kb][2],   acc[2*kb][3]);   yh[kb][1] = h;
        yl[kb][1] = cvt2(acc[2*kb][2] - bl(h),    acc[2*kb][3] - bh(h));
        h = cvt2(acc[2*kb+1][0], acc[2*kb+1][1]); yh[kb][2] = h;
        yl[kb][2] = cvt2(acc[2*kb+1][0] - bl(h),  acc[2*kb+1][1] - bh(h));
        h = cvt2(acc[2*kb+1][2], acc[2*kb+1][3]); yh[kb][3] = h;
        yl[kb][3] = cvt2(acc[2*kb+1][2] - bl(h),  acc[2*kb+1][3] - bh(h));
    }

    // ================= Phase 2: Z = Y V^T, out = X - Z  (4 n-chunks) ========
    #pragma unroll
    for (int j = 0; j < 4; j++) {
        if (j < 3) { CP_WAIT(1); } else { CP_WAIT(0); }
        __syncthreads();
        uint32_t bufVh = (j & 1) ? (sb + OFF_A0) : sStage;
        uint32_t bufVl = bufVh + 16384;

        float z[16][4];
        #pragma unroll
        for (int i = 0; i < 16; i++)
            z[i][0] = z[i][1] = z[i][2] = z[i][3] = 0.f;

        #pragma unroll
        for (int ks = 0; ks < 4; ks++) {
            uint32_t ic = (lcolb + ks * 32) ^ xr;
            #pragma unroll
            for (int p = 0; p < 8; p++) {
                uint32_t ro = (lrow + p * 16) * 128;
                uint32_t bhr[4], blr[4];
                ldsm4(bhr, bufVh + ro + ic);
                ldsm4(blr, bufVl + ro + ic);
                mma16816(z[2 * p],     yh[ks], bhr[0], bhr[2]);
                mma16816(z[2 * p],     yh[ks], blr[0], blr[2]);
                mma16816(z[2 * p],     yl[ks], bhr[0], bhr[2]);
                mma16816(z[2 * p + 1], yh[ks], bhr[1], bhr[3]);
                mma16816(z[2 * p + 1], yh[ks], blr[1], blr[3]);
                mma16816(z[2 * p + 1], yl[ks], bhr[1], bhr[3]);
            }
        }
        __syncthreads();             // done reading this V buffer
        if (j < 2) {
            uint32_t nh = (j & 1) ? (sb + OFF_A0) : sStage;
            issueV(j + 2, nh, nh + 16384);
            CP_COMMIT();
        }

        int r0 = m0 + mw + (lane >> 2);
        const float* x0p = x + (size_t)r0 * Dv;
        const float* x1p = x0p + 8 * Dv;
        float* o0 = out + (size_t)r0 * Dv;
        float* o1 = o0 + 8 * Dv;
        int cbase = (j << 7) + ((lane & 3) << 1);
        #pragma unroll
        for (int nt = 0; nt < 16; nt++) {
            int cc = cbase + nt * 8;
            float2 a0 = *(const float2*)(x0p + cc);
            float2 a1 = *(const float2*)(x1p + cc);
            float2 w0 = make_float2(a0.x - z[nt][0], a0.y - z[nt][1]);
            float2 w1 = make_float2(a1.x - z[nt][2], a1.y - z[nt][3]);
            *(float2*)(o0 + cc) = w0;
            *(float2*)(o1 + cc) = w1;
        }
    }

    if (outSldj != nullptr && tid < TM) {
        outSldj[m0 + tid] = sldj[m0 + tid];
    }
}

extern "C" void kernel_launch(void* const* d_in, const int* in_sizes, int n_in,
                              void* d_out, int out_size) {
    const float* x    = (const float*)d_in[0];   // (B, D)
    const float* sldj = (const float*)d_in[1];   // (B,)
    const float* P    = (const float*)d_in[2];   // (D, R)
    int BD = in_sizes[0];
    int Bn = in_sizes[1];
    (void)n_in;
    float* out = (float*)d_out;
    float* osl = (out_size >= BD + Bn) ? (out + BD) : nullptr;

    k_norm      <<<Rv, 256>>>(P);
    k_gram_packV<<<Rv, 256>>>();
    k_winv      <<<1, 1024>>>();
    k_packA2    <<<8, 256>>>();

    cudaFuncSetAttribute(k_gemm, cudaFuncAttributeMaxDynamicSharedMemorySize, SMEM_BYTES);
    k_gemm<<<Bn / TM, NTHREADS, SMEM_BYTES>>>(x, out, sldj, osl);
}